// round 1
// baseline (speedup 1.0000x reference)
#include <cuda_runtime.h>
#include <cstdint>
#include <cstdio>

#define BS_    2
#define SEQ    1024
#define DMODEL 1024
#define NH     16
#define HD     64
#define MM     32
#define ROWS   (BS_*SEQ)

// -------- scratch (device globals; no allocation allowed) --------
__device__ float g_h1 [ROWS*DMODEL];
__device__ float g_qkv[ROWS*3*DMODEL];
__device__ float g_mem[ROWS*DMODEL];
__device__ float g_att[ROWS*DMODEL];
__device__ float g_hid[ROWS*DMODEL];
__device__ float g_h2 [ROWS*DMODEL];
__device__ float g_ff [ROWS*4*DMODEL];

__device__ __forceinline__ float gelu_new(float x) {
    float x3 = x * x * x;
    float t  = tanhf(0.7978845608028654f * (x + 0.044715f * x3));
    return 0.5f * x * (1.f + t);
}

// ---------------- LayerNorm: one block per row (1024 cols) ----------------
__global__ void __launch_bounds__(256) ln_kernel(
    const float* __restrict__ x, const float* __restrict__ g,
    const float* __restrict__ b, float* __restrict__ y)
{
    const int row = blockIdx.x, tid = threadIdx.x;
    const float* xr = x + (size_t)row * DMODEL;
    float4 v = *(const float4*)(xr + tid * 4);
    float s  = v.x + v.y + v.z + v.w;
    float s2 = v.x*v.x + v.y*v.y + v.z*v.z + v.w*v.w;
    __shared__ float rs[8], rs2[8];
    #pragma unroll
    for (int o = 16; o; o >>= 1) {
        s  += __shfl_xor_sync(0xffffffffu, s,  o);
        s2 += __shfl_xor_sync(0xffffffffu, s2, o);
    }
    const int w = tid >> 5, l = tid & 31;
    if (!l) { rs[w] = s; rs2[w] = s2; }
    __syncthreads();
    s = 0.f; s2 = 0.f;
    #pragma unroll
    for (int i = 0; i < 8; i++) { s += rs[i]; s2 += rs2[i]; }
    const float mean = s * (1.f / DMODEL);
    const float var  = s2 * (1.f / DMODEL) - mean * mean;
    const float rstd = rsqrtf(var + 1e-5f);
    const int c = tid * 4;
    float4 gg = *(const float4*)(g + c);
    float4 bb = *(const float4*)(b + c);
    float4 o;
    o.x = (v.x - mean) * rstd * gg.x + bb.x;
    o.y = (v.y - mean) * rstd * gg.y + bb.y;
    o.z = (v.z - mean) * rstd * gg.z + bb.z;
    o.w = (v.w - mean) * rstd * gg.w + bb.w;
    *(float4*)(y + (size_t)row * DMODEL + c) = o;
}

// ---------------- GEMM: C[M,N] = A[M,K] @ B[K,N] + bias, fused epilogues ----
// EPI 0: +bias
// EPI 1: h = (1-g)*(AB+bias) + g*aux1 + aux2      (gated combine + residual)
// EPI 2: gelu_new(AB+bias)
// EPI 3: AB+bias + aux1                            (final residual)
template<int EPI>
__global__ void __launch_bounds__(256) gemm_kernel(
    const float* __restrict__ A, const float* __restrict__ B,
    const float* __restrict__ bias, float* __restrict__ C,
    int M, int N, int K,
    const float* __restrict__ aux1, const float* __restrict__ aux2,
    const float* __restrict__ gp)
{
    __shared__ float As[16][132];   // [BK][BM+4] transposed, padded
    __shared__ float Bs[16][128];   // [BK][BN]
    const int tid = threadIdx.x;
    const int ty = tid >> 4, tx = tid & 15;
    const int bm = blockIdx.y, bn = blockIdx.x;
    const int rA = tid >> 2;           // 0..63
    const int kA = (tid & 3) * 4;      // 0,4,8,12
    const int rB = tid >> 5;           // 0..7
    const int nB = (tid & 31) * 4;     // 0..124
    const float* Ab = A + (size_t)bm * 128 * K;
    const float* Bb = B + (size_t)bn * 128;
    float acc[8][8];
    #pragma unroll
    for (int i = 0; i < 8; i++)
        #pragma unroll
        for (int j = 0; j < 8; j++) acc[i][j] = 0.f;

    for (int kt = 0; kt < K; kt += 16) {
        float4 a0 = *(const float4*)(Ab + (size_t)rA        * K + kt + kA);
        float4 a1 = *(const float4*)(Ab + (size_t)(rA + 64) * K + kt + kA);
        float4 b0 = *(const float4*)(Bb + (size_t)(kt + rB)     * N + nB);
        float4 b1 = *(const float4*)(Bb + (size_t)(kt + rB + 8) * N + nB);
        As[kA+0][rA] = a0.x; As[kA+1][rA] = a0.y; As[kA+2][rA] = a0.z; As[kA+3][rA] = a0.w;
        As[kA+0][rA+64] = a1.x; As[kA+1][rA+64] = a1.y; As[kA+2][rA+64] = a1.z; As[kA+3][rA+64] = a1.w;
        *(float4*)&Bs[rB][nB]     = b0;
        *(float4*)&Bs[rB + 8][nB] = b1;
        __syncthreads();
        #pragma unroll
        for (int kk = 0; kk < 16; kk++) {
            float a[8], bf[8];
            *(float4*)&a[0]  = *(const float4*)&As[kk][ty * 8];
            *(float4*)&a[4]  = *(const float4*)&As[kk][ty * 8 + 4];
            *(float4*)&bf[0] = *(const float4*)&Bs[kk][tx * 8];
            *(float4*)&bf[4] = *(const float4*)&Bs[kk][tx * 8 + 4];
            #pragma unroll
            for (int i = 0; i < 8; i++)
                #pragma unroll
                for (int j = 0; j < 8; j++) acc[i][j] += a[i] * bf[j];
        }
        __syncthreads();
    }
    float g = 0.f;
    if (EPI == 1) g = *gp;
    #pragma unroll
    for (int i = 0; i < 8; i++) {
        const int r  = bm * 128 + ty * 8 + i;
        const int c0 = bn * 128 + tx * 8;
        const size_t idx = (size_t)r * N + c0;
        #pragma unroll
        for (int j = 0; j < 8; j++) {
            float v = acc[i][j] + bias[c0 + j];
            if (EPI == 1) v = (1.f - g) * v + g * aux1[idx + j] + aux2[idx + j];
            if (EPI == 2) v = gelu_new(v);
            if (EPI == 3) v = v + aux1[idx + j];
            C[idx + j] = v;
        }
    }
}

// ---------------- KNN memory attention (bandwidth-bound on mem_kv) ----------
// one block per (b,s) row; 256 threads; head h = tid>>4 owns lanes t=tid&15
__global__ void __launch_bounds__(256) memattn_kernel(
    const float* __restrict__ qkv, const float* __restrict__ mkv,
    float* __restrict__ outm)
{
    const int row = blockIdx.x, tid = threadIdx.x;
    __shared__ float sc[NH * MM];
    float4 qv = *(const float4*)(qkv + (size_t)row * 3072 + tid * 4);
    qv.x *= 0.125f; qv.y *= 0.125f; qv.z *= 0.125f; qv.w *= 0.125f;
    const float* kbase = mkv + (size_t)row * MM * 2 * DMODEL;
    const int h = tid >> 4;
    #pragma unroll 4
    for (int m = 0; m < MM; m++) {
        float4 kk = *(const float4*)(kbase + (size_t)m * 2 * DMODEL + tid * 4);
        float d = qv.x * kk.x + qv.y * kk.y + qv.z * kk.z + qv.w * kk.w;
        #pragma unroll
        for (int o = 8; o; o >>= 1) d += __shfl_xor_sync(0xffffffffu, d, o);
        if ((tid & 15) == 0) sc[h * MM + m] = d;
    }
    __syncthreads();
    if (tid < NH) {
        float mx = -1e30f;
        #pragma unroll
        for (int m = 0; m < MM; m++) mx = fmaxf(mx, sc[tid * MM + m]);
        float s = 0.f;
        #pragma unroll
        for (int m = 0; m < MM; m++) {
            float e = __expf(sc[tid * MM + m] - mx);
            sc[tid * MM + m] = e; s += e;
        }
        float inv = 1.f / s;
        #pragma unroll
        for (int m = 0; m < MM; m++) sc[tid * MM + m] *= inv;
    }
    __syncthreads();
    float4 acc = make_float4(0.f, 0.f, 0.f, 0.f);
    #pragma unroll 4
    for (int m = 0; m < MM; m++) {
        float w = sc[h * MM + m];
        float4 vv = *(const float4*)(kbase + (size_t)m * 2 * DMODEL + DMODEL + tid * 4);
        acc.x += w * vv.x; acc.y += w * vv.y; acc.z += w * vv.z; acc.w += w * vv.w;
    }
    *(float4*)(outm + (size_t)row * DMODEL + tid * 4) = acc;
}

// ---------------- causal flash attention, fp32, 64x64 tiles -----------------
#define QST 65
#define FLASH_SMEM ((2 * 64 * QST + 64 * 64) * 4)
__global__ void __launch_bounds__(256) flash_kernel(
    const float* __restrict__ qkv, float* __restrict__ out)
{
    extern __shared__ float sm[];
    float* Qs = sm;                 // [64][QST]  (Q, scaled)
    float* KP = sm + 64 * QST;      // [64][QST]  (K, then reused for P)
    float* Vs = sm + 2 * 64 * QST;  // [64][64]
    const int tid = threadIdx.x;
    const int ty = tid >> 4, tx = tid & 15;
    const int qt = blockIdx.x;
    const int b = blockIdx.y >> 4, h = blockIdx.y & 15;
    const int qbase = qt * 64;
    const size_t srow = (size_t)b * SEQ;
    const int li = tid >> 2;
    const int lc0 = (tid & 3) * 4;

    { // load Q tile (scaled by 1/sqrt(HD))
        const float* gq = qkv + (srow + qbase + li) * (size_t)3072 + h * 64;
        #pragma unroll
        for (int u = 0; u < 4; u++) {
            const int c = lc0 + u * 16;
            float4 v = *(const float4*)(gq + c);
            Qs[li*QST+c]   = v.x * 0.125f; Qs[li*QST+c+1] = v.y * 0.125f;
            Qs[li*QST+c+2] = v.z * 0.125f; Qs[li*QST+c+3] = v.w * 0.125f;
        }
    }
    float m_i[4], l_i[4], o[4][4];
    #pragma unroll
    for (int v = 0; v < 4; v++) {
        m_i[v] = -1e30f; l_i[v] = 0.f;
        o[v][0] = o[v][1] = o[v][2] = o[v][3] = 0.f;
    }

    for (int kt = 0; kt <= qt; kt++) {
        __syncthreads();
        const int kbase = kt * 64;
        const float* gk = qkv + (srow + kbase + li) * (size_t)3072 + 1024 + h * 64;
        const float* gv = qkv + (srow + kbase + li) * (size_t)3072 + 2048 + h * 64;
        #pragma unroll
        for (int u = 0; u < 4; u++) {
            const int c = lc0 + u * 16;
            float4 kv = *(const float4*)(gk + c);
            KP[li*QST+c]   = kv.x; KP[li*QST+c+1] = kv.y;
            KP[li*QST+c+2] = kv.z; KP[li*QST+c+3] = kv.w;
            float4 vv = *(const float4*)(gv + c);
            *(float4*)&Vs[li * 64 + c] = vv;
        }
        __syncthreads();
        float s[4][4];
        #pragma unroll
        for (int v = 0; v < 4; v++) s[v][0] = s[v][1] = s[v][2] = s[v][3] = 0.f;
        #pragma unroll 8
        for (int dd = 0; dd < 64; dd++) {
            float a[4], bf[4];
            #pragma unroll
            for (int v = 0; v < 4; v++) a[v]  = Qs[(ty * 4 + v) * QST + dd];
            #pragma unroll
            for (int u = 0; u < 4; u++) bf[u] = KP[(tx * 4 + u) * QST + dd];
            #pragma unroll
            for (int v = 0; v < 4; v++)
                #pragma unroll
                for (int u = 0; u < 4; u++) s[v][u] += a[v] * bf[u];
        }
        if (kt == qt) {
            #pragma unroll
            for (int v = 0; v < 4; v++)
                #pragma unroll
                for (int u = 0; u < 4; u++)
                    if (tx * 4 + u > ty * 4 + v) s[v][u] = -1e30f;
        }
        float mnew[4], alpha[4], p[4][4], rsum[4];
        #pragma unroll
        for (int v = 0; v < 4; v++) {
            float mx = fmaxf(fmaxf(s[v][0], s[v][1]), fmaxf(s[v][2], s[v][3]));
            #pragma unroll
            for (int off = 8; off; off >>= 1)
                mx = fmaxf(mx, __shfl_xor_sync(0xffffffffu, mx, off));
            mnew[v]  = fmaxf(m_i[v], mx);
            alpha[v] = __expf(m_i[v] - mnew[v]);
            float rs = 0.f;
            #pragma unroll
            for (int u = 0; u < 4; u++) { p[v][u] = __expf(s[v][u] - mnew[v]); rs += p[v][u]; }
            #pragma unroll
            for (int off = 8; off; off >>= 1)
                rs += __shfl_xor_sync(0xffffffffu, rs, off);
            rsum[v] = rs;
        }
        #pragma unroll
        for (int v = 0; v < 4; v++) {
            l_i[v] = alpha[v] * l_i[v] + rsum[v];
            m_i[v] = mnew[v];
            o[v][0] *= alpha[v]; o[v][1] *= alpha[v]; o[v][2] *= alpha[v]; o[v][3] *= alpha[v];
        }
        __syncthreads();     // everyone done reading K from KP
        #pragma unroll
        for (int v = 0; v < 4; v++)
            #pragma unroll
            for (int u = 0; u < 4; u++)
                KP[(ty * 4 + v) * QST + tx * 4 + u] = p[v][u];  // P, i-major
        __syncthreads();
        #pragma unroll 4
        for (int jj = 0; jj < 64; jj++) {
            float4 bv = *(const float4*)&Vs[jj * 64 + tx * 4];
            #pragma unroll
            for (int v = 0; v < 4; v++) {
                float a = KP[(ty * 4 + v) * QST + jj];
                o[v][0] += a * bv.x; o[v][1] += a * bv.y;
                o[v][2] += a * bv.z; o[v][3] += a * bv.w;
            }
        }
    }
    #pragma unroll
    for (int v = 0; v < 4; v++) {
        const float inv = 1.f / l_i[v];
        const int qi = qbase + ty * 4 + v;
        float4 ov = make_float4(o[v][0]*inv, o[v][1]*inv, o[v][2]*inv, o[v][3]*inv);
        *(float4*)(out + (srow + qi) * (size_t)DMODEL + h * 64 + tx * 4) = ov;
    }
}

// ------------------------------ launcher ------------------------------------
extern "C" void kernel_launch(void* const* d_in, const int* in_sizes, int n_in,
                              void* d_out, int out_size)
{
    (void)in_sizes; (void)n_in; (void)out_size;
    const float* prev  = (const float*)d_in[0];
    const float* memkv = (const float*)d_in[1];
    const float* gval  = (const float*)d_in[2];
    const float* ln1g  = (const float*)d_in[3];
    const float* ln1b  = (const float*)d_in[4];
    const float* attnw = (const float*)d_in[5];
    const float* attnb = (const float*)d_in[6];
    const float* cprw  = (const float*)d_in[7];
    const float* cprb  = (const float*)d_in[8];
    const float* ln2g  = (const float*)d_in[9];
    const float* ln2b  = (const float*)d_in[10];
    const float* fcw   = (const float*)d_in[11];
    const float* fcb   = (const float*)d_in[12];
    const float* pw    = (const float*)d_in[13];
    const float* pb    = (const float*)d_in[14];
    float* out = (float*)d_out;

    float *h1, *qkv, *mem, *att, *hid, *h2, *ff;
    cudaGetSymbolAddress((void**)&h1,  g_h1);
    cudaGetSymbolAddress((void**)&qkv, g_qkv);
    cudaGetSymbolAddress((void**)&mem, g_mem);
    cudaGetSymbolAddress((void**)&att, g_att);
    cudaGetSymbolAddress((void**)&hid, g_hid);
    cudaGetSymbolAddress((void**)&h2,  g_h2);
    cudaGetSymbolAddress((void**)&ff,  g_ff);

    cudaFuncSetAttribute(flash_kernel,
        cudaFuncAttributeMaxDynamicSharedMemorySize, FLASH_SMEM);

    // 1) LN1
    ln_kernel<<<ROWS, 256>>>(prev, ln1g, ln1b, h1);
    // 2) QKV = h1 @ c_attn_w + b  [2048,3072]
    gemm_kernel<0><<<dim3(24, 16), 256>>>(h1, attnw, attnb, qkv,
        ROWS, 3 * DMODEL, DMODEL, nullptr, nullptr, nullptr);
    // 3) memory attention (uses q from qkv)
    memattn_kernel<<<ROWS, 256>>>(qkv, memkv, mem);
    // 4) causal self-attention -> merged [2048,1024]
    flash_kernel<<<dim3(SEQ / 64, BS_ * NH), 256, FLASH_SMEM>>>(qkv, att);
    // 5) h = (1-g)*(att @ c_proj + b) + g*mem + prev
    gemm_kernel<1><<<dim3(8, 16), 256>>>(att, cprw, cprb, hid,
        ROWS, DMODEL, DMODEL, mem, prev, gval);
    // 6) LN2
    ln_kernel<<<ROWS, 256>>>(hid, ln2g, ln2b, h2);
    // 7) ff = gelu(h2 @ fc_w + fc_b)  [2048,4096]
    gemm_kernel<2><<<dim3(32, 16), 256>>>(h2, fcw, fcb, ff,
        ROWS, 4 * DMODEL, DMODEL, nullptr, nullptr, nullptr);
    // 8) out = ff @ proj_w + proj_b + hid
    gemm_kernel<3><<<dim3(8, 16), 256>>>(ff, pw, pb, out,
        ROWS, DMODEL, 4 * DMODEL, hid, nullptr, nullptr);
}

// round 3
// speedup vs baseline: 1.8650x; 1.8650x over previous
#include <cuda_runtime.h>
#include <cuda_bf16.h>
#include <cstdint>

#define BS_    2
#define SEQ    1024
#define DMODEL 1024
#define NH     16
#define HD     64
#define MM     32
#define ROWS   (BS_*SEQ)

// ---------------- scratch (device globals) ----------------
__device__ float g_qkv[ROWS*3*DMODEL];
__device__ float g_mem[ROWS*DMODEL];
__device__ float g_hid[ROWS*DMODEL];
__device__ __nv_bfloat16 g_h1h[ROWS*DMODEL],  g_h1l[ROWS*DMODEL];
__device__ __nv_bfloat16 g_atth[ROWS*DMODEL], g_attl[ROWS*DMODEL];
__device__ __nv_bfloat16 g_h2h[ROWS*DMODEL],  g_h2l[ROWS*DMODEL];
__device__ __nv_bfloat16 g_ffh[ROWS*4*DMODEL], g_ffl[ROWS*4*DMODEL];
__device__ __nv_bfloat16 g_wqh[DMODEL*3*DMODEL], g_wql[DMODEL*3*DMODEL];
__device__ __nv_bfloat16 g_wph[DMODEL*DMODEL],   g_wpl[DMODEL*DMODEL];
__device__ __nv_bfloat16 g_wfh[DMODEL*4*DMODEL], g_wfl[DMODEL*4*DMODEL];
__device__ __nv_bfloat16 g_woh[4*DMODEL*DMODEL], g_wol[4*DMODEL*DMODEL];

// ---------------- helpers ----------------
__device__ __forceinline__ uint32_t smem_to_u32(const void* p) {
    uint32_t a;
    asm("{ .reg .u64 t; cvta.to.shared.u64 t, %1; cvt.u32.u64 %0, t; }" : "=r"(a) : "l"(p));
    return a;
}
__device__ __forceinline__ void cp16(uint32_t s, const void* g) {
    asm volatile("cp.async.cg.shared.global [%0], [%1], 16;" :: "r"(s), "l"(g));
}
#define CP_COMMIT() asm volatile("cp.async.commit_group;" ::: "memory")
#define CP_WAIT1()  asm volatile("cp.async.wait_group 1;" ::: "memory")

__device__ __forceinline__ void mma16816(float* d, const uint32_t* a, const uint32_t* b) {
    asm volatile(
      "mma.sync.aligned.m16n8k16.row.col.f32.bf16.bf16.f32 "
      "{%0,%1,%2,%3}, {%4,%5,%6,%7}, {%8,%9}, {%0,%1,%2,%3};"
      : "+f"(d[0]), "+f"(d[1]), "+f"(d[2]), "+f"(d[3])
      : "r"(a[0]), "r"(a[1]), "r"(a[2]), "r"(a[3]), "r"(b[0]), "r"(b[1]));
}

__device__ __forceinline__ float gelu_new(float x) {
    float x3 = x * x * x;
    float t  = tanhf(0.7978845608028654f * (x + 0.044715f * x3));
    return 0.5f * x * (1.f + t);
}
__device__ __forceinline__ uint32_t pack_bf2(float x, float y) {
    __nv_bfloat162 t = __floats2bfloat162_rn(x, y);
    return *reinterpret_cast<uint32_t*>(&t);
}
__device__ __forceinline__ float bf_hi(float x) {
    return __bfloat162float(__float2bfloat16(x));
}

// ---------------- weight convert: W[K,N] f32 -> Whi/Wlo [N,K] bf16 --------
__global__ void __launch_bounds__(256) wconv_kernel(
    const float* __restrict__ W, __nv_bfloat16* __restrict__ hi,
    __nv_bfloat16* __restrict__ lo, int K, int N)
{
    __shared__ float s[32][33];
    const int tx = threadIdx.x & 31, ty = threadIdx.x >> 5;
    const int n0 = blockIdx.x * 32, k0 = blockIdx.y * 32;
    #pragma unroll
    for (int i = 0; i < 4; i++)
        s[ty + 8*i][tx] = W[(size_t)(k0 + ty + 8*i) * N + n0 + tx];
    __syncthreads();
    #pragma unroll
    for (int i = 0; i < 4; i++) {
        int n = ty + 8*i;
        float v = s[tx][n];
        float h = bf_hi(v);
        size_t o = (size_t)(n0 + n) * K + k0 + tx;
        hi[o] = __float2bfloat16(v);
        lo[o] = __float2bfloat16(v - h);
    }
}

// ---------------- LayerNorm -> hi/lo bf16 ----------------
__global__ void __launch_bounds__(256) ln_kernel(
    const float* __restrict__ x, const float* __restrict__ g,
    const float* __restrict__ b, __nv_bfloat16* __restrict__ yh,
    __nv_bfloat16* __restrict__ yl)
{
    const int row = blockIdx.x, tid = threadIdx.x;
    const float* xr = x + (size_t)row * DMODEL;
    float4 v = *(const float4*)(xr + tid * 4);
    float s  = v.x + v.y + v.z + v.w;
    float s2 = v.x*v.x + v.y*v.y + v.z*v.z + v.w*v.w;
    __shared__ float rs[8], rs2[8];
    #pragma unroll
    for (int o = 16; o; o >>= 1) {
        s  += __shfl_xor_sync(0xffffffffu, s,  o);
        s2 += __shfl_xor_sync(0xffffffffu, s2, o);
    }
    const int w = tid >> 5, l = tid & 31;
    if (!l) { rs[w] = s; rs2[w] = s2; }
    __syncthreads();
    s = 0.f; s2 = 0.f;
    #pragma unroll
    for (int i = 0; i < 8; i++) { s += rs[i]; s2 += rs2[i]; }
    const float mean = s * (1.f / DMODEL);
    const float var  = s2 * (1.f / DMODEL) - mean * mean;
    const float rstd = rsqrtf(var + 1e-5f);
    const int c = tid * 4;
    float4 gg = *(const float4*)(g + c);
    float4 bb = *(const float4*)(b + c);
    float4 o;
    o.x = (v.x - mean) * rstd * gg.x + bb.x;
    o.y = (v.y - mean) * rstd * gg.y + bb.y;
    o.z = (v.z - mean) * rstd * gg.z + bb.z;
    o.w = (v.w - mean) * rstd * gg.w + bb.w;
    uint2 hh, ll;
    hh.x = pack_bf2(o.x, o.y); hh.y = pack_bf2(o.z, o.w);
    ll.x = pack_bf2(o.x - bf_hi(o.x), o.y - bf_hi(o.y));
    ll.y = pack_bf2(o.z - bf_hi(o.z), o.w - bf_hi(o.w));
    const size_t idx = (size_t)row * DMODEL + c;
    *(uint2*)(yh + idx) = hh;
    *(uint2*)(yl + idx) = ll;
}

// ---------------- mma.sync bf16x3 GEMM --------------------------------------
// C[M,N] = A[M,K] @ B^T (B stored [N,K]); A,B as hi/lo bf16 pairs.
// CTA tile 128x128, 8 warps (2x4) of 64x32 each. K-chunk 32, cp.async x2 buf.
// SMEM row stride 40 bf16 (80B) -> conflict-free quad-pattern frag loads.
// EPI 0: +bias->f32 | 1: gated+residual->f32 | 2: gelu->bf16 hi/lo | 3: +bias+aux1->f32
#define PADK    40
#define STAGE_B (128*PADK*2)            // 10240 B per array
#define GSTAGE  (4*STAGE_B)             // 40960 B per stage
#define GEMM_SMEM (2*GSTAGE)            // 81920 B

template<int EPI>
__global__ void __launch_bounds__(256) gemm_mma_kernel(
    const __nv_bfloat16* __restrict__ Ah, const __nv_bfloat16* __restrict__ Al,
    const __nv_bfloat16* __restrict__ Bh, const __nv_bfloat16* __restrict__ Bl,
    const float* __restrict__ bias,
    float* __restrict__ Cf, __nv_bfloat16* __restrict__ Ch, __nv_bfloat16* __restrict__ Cl,
    int M, int N, int K,
    const float* __restrict__ aux1, const float* __restrict__ aux2,
    const float* __restrict__ gp)
{
    extern __shared__ char smp[];
    const uint32_t sb = smem_to_u32(smp);
    const int tid = threadIdx.x;
    const int wid = tid >> 5, lane = tid & 31;
    const int wm = wid & 1, wn = wid >> 1;           // warp tile: 64x32
    const int bm = blockIdx.y, bn = blockIdx.x;
    const int NC = K >> 5;

    const size_t Abase = (size_t)bm * 128 * K;
    const size_t Bbase = (size_t)bn * 128 * K;

    float acc[4][4][4];
    #pragma unroll
    for (int i = 0; i < 4; i++)
        #pragma unroll
        for (int j = 0; j < 4; j++)
            #pragma unroll
            for (int x = 0; x < 4; x++) acc[i][j][x] = 0.f;

    // cp.async mapping: per array, chunk = (row, 16B quarter); 2 chunks/thread
    const int crow = tid >> 2;          // 0..63
    const int cq   = tid & 3;           // 16B quarter within 64B row

    auto issue = [&](int buf, int kt) {
        const int k0 = kt << 5;
        const uint32_t sbase = sb + buf * GSTAGE;
        #pragma unroll
        for (int h = 0; h < 2; h++) {
            const int row = crow + h * 64;
            const uint32_t so = (uint32_t)(row * (PADK*2) + cq * 16);
            const size_t go = (size_t)row * K + k0 + cq * 8;
            cp16(sbase + so,               Ah + Abase + go);
            cp16(sbase + STAGE_B + so,     Al + Abase + go);
            cp16(sbase + 2*STAGE_B + so,   Bh + Bbase + go);
            cp16(sbase + 3*STAGE_B + so,   Bl + Bbase + go);
        }
    };

    issue(0, 0); CP_COMMIT();
    if (NC > 1) issue(1, 1);
    CP_COMMIT();

    const int r = lane >> 2, q = lane & 3;

    for (int c = 0; c < NC; c++) {
        CP_WAIT1();
        __syncthreads();
        const uint32_t* Sa_h = (const uint32_t*)(smp + (c & 1) * GSTAGE);
        const uint32_t* Sa_l = Sa_h + STAGE_B/4;
        const uint32_t* Sb_h = Sa_h + 2*(STAGE_B/4);
        const uint32_t* Sb_l = Sa_h + 3*(STAGE_B/4);
        #pragma unroll
        for (int ks = 0; ks < 2; ks++) {            // two k16 sub-steps
            const int kb = ks * 8;                   // (ks*16)/2
            uint32_t ah[4][4], al[4][4], bh[4][2], bl[4][2];
            #pragma unroll
            for (int mt = 0; mt < 4; mt++) {
                const int m0 = wm * 64 + mt * 16 + r;
                ah[mt][0] = Sa_h[m0*20 + kb + q];
                ah[mt][1] = Sa_h[(m0+8)*20 + kb + q];
                ah[mt][2] = Sa_h[m0*20 + kb + 4 + q];
                ah[mt][3] = Sa_h[(m0+8)*20 + kb + 4 + q];
                al[mt][0] = Sa_l[m0*20 + kb + q];
                al[mt][1] = Sa_l[(m0+8)*20 + kb + q];
                al[mt][2] = Sa_l[m0*20 + kb + 4 + q];
                al[mt][3] = Sa_l[(m0+8)*20 + kb + 4 + q];
            }
            #pragma unroll
            for (int nt = 0; nt < 4; nt++) {
                const int n0 = wn * 32 + nt * 8 + r;
                bh[nt][0] = Sb_h[n0*20 + kb + q];
                bh[nt][1] = Sb_h[n0*20 + kb + 4 + q];
                bl[nt][0] = Sb_l[n0*20 + kb + q];
                bl[nt][1] = Sb_l[n0*20 + kb + 4 + q];
            }
            #pragma unroll
            for (int mt = 0; mt < 4; mt++)
                #pragma unroll
                for (int nt = 0; nt < 4; nt++) {
                    mma16816(acc[mt][nt], ah[mt], bh[nt]);
                    mma16816(acc[mt][nt], ah[mt], bl[nt]);
                    mma16816(acc[mt][nt], al[mt], bh[nt]);
                }
        }
        __syncthreads();
        if (c + 2 < NC) issue(c & 1, c + 2);
        CP_COMMIT();
    }

    // ---------------- epilogue ----------------
    const float g = (EPI == 1) ? *gp : 0.f;
    #pragma unroll
    for (int mt = 0; mt < 4; mt++) {
        #pragma unroll
        for (int nt = 0; nt < 4; nt++) {
            const int col = bn * 128 + wn * 32 + nt * 8 + q * 2;
            const float2 bb = *(const float2*)(bias + col);
            #pragma unroll
            for (int hh = 0; hh < 2; hh++) {
                const int row = bm * 128 + wm * 64 + mt * 16 + r + hh * 8;
                const size_t o = (size_t)row * N + col;
                float v0 = acc[mt][nt][hh*2+0] + bb.x;
                float v1 = acc[mt][nt][hh*2+1] + bb.y;
                if (EPI == 1) {
                    float2 a1 = *(const float2*)(aux1 + o);
                    float2 a2 = *(const float2*)(aux2 + o);
                    v0 = (1.f - g) * v0 + g * a1.x + a2.x;
                    v1 = (1.f - g) * v1 + g * a1.y + a2.y;
                }
                if (EPI == 3) {
                    float2 a1 = *(const float2*)(aux1 + o);
                    v0 += a1.x; v1 += a1.y;
                }
                if (EPI == 2) {
                    v0 = gelu_new(v0); v1 = gelu_new(v1);
                    *(uint32_t*)(Ch + o) = pack_bf2(v0, v1);
                    *(uint32_t*)(Cl + o) = pack_bf2(v0 - bf_hi(v0), v1 - bf_hi(v1));
                } else {
                    *(float2*)(Cf + o) = make_float2(v0, v1);
                }
            }
        }
    }
}

// ---------------- KNN memory attention ----------------
__global__ void __launch_bounds__(256) memattn_kernel(
    const float* __restrict__ qkv, const float* __restrict__ mkv,
    float* __restrict__ outm)
{
    const int row = blockIdx.x, tid = threadIdx.x;
    __shared__ float sc[NH * MM];
    float4 qv = *(const float4*)(qkv + (size_t)row * 3072 + tid * 4);
    qv.x *= 0.125f; qv.y *= 0.125f; qv.z *= 0.125f; qv.w *= 0.125f;
    const float* kbase = mkv + (size_t)row * MM * 2 * DMODEL;
    const int h = tid >> 4;
    #pragma unroll 4
    for (int m = 0; m < MM; m++) {
        float4 kk = *(const float4*)(kbase + (size_t)m * 2 * DMODEL + tid * 4);
        float d = qv.x * kk.x + qv.y * kk.y + qv.z * kk.z + qv.w * kk.w;
        #pragma unroll
        for (int o = 8; o; o >>= 1) d += __shfl_xor_sync(0xffffffffu, d, o);
        if ((tid & 15) == 0) sc[h * MM + m] = d;
    }
    __syncthreads();
    if (tid < NH) {
        float mx = -1e30f;
        #pragma unroll
        for (int m = 0; m < MM; m++) mx = fmaxf(mx, sc[tid * MM + m]);
        float s = 0.f;
        #pragma unroll
        for (int m = 0; m < MM; m++) {
            float e = __expf(sc[tid * MM + m] - mx);
            sc[tid * MM + m] = e; s += e;
        }
        float inv = 1.f / s;
        #pragma unroll
        for (int m = 0; m < MM; m++) sc[tid * MM + m] *= inv;
    }
    __syncthreads();
    float4 acc = make_float4(0.f, 0.f, 0.f, 0.f);
    #pragma unroll 4
    for (int m = 0; m < MM; m++) {
        float w = sc[h * MM + m];
        float4 vv = *(const float4*)(kbase + (size_t)m * 2 * DMODEL + DMODEL + tid * 4);
        acc.x += w * vv.x; acc.y += w * vv.y; acc.z += w * vv.z; acc.w += w * vv.w;
    }
    *(float4*)(outm + (size_t)row * DMODEL + tid * 4) = acc;
}

// ---------------- causal flash attention, fp32, writes hi/lo bf16 ----------
#define QST 65
#define FLASH_SMEM ((2 * 64 * QST + 64 * 64) * 4)
__global__ void __launch_bounds__(256) flash_kernel(
    const float* __restrict__ qkv, __nv_bfloat16* __restrict__ outh,
    __nv_bfloat16* __restrict__ outl)
{
    extern __shared__ float sm[];
    float* Qs = sm;
    float* KP = sm + 64 * QST;
    float* Vs = sm + 2 * 64 * QST;
    const int tid = threadIdx.x;
    const int ty = tid >> 4, tx = tid & 15;
    const int qt = blockIdx.x;
    const int b = blockIdx.y >> 4, h = blockIdx.y & 15;
    const int qbase = qt * 64;
    const size_t srow = (size_t)b * SEQ;
    const int li = tid >> 2;
    const int lc0 = (tid & 3) * 4;

    {
        const float* gq = qkv + (srow + qbase + li) * (size_t)3072 + h * 64;
        #pragma unroll
        for (int u = 0; u < 4; u++) {
            const int c = lc0 + u * 16;
            float4 v = *(const float4*)(gq + c);
            Qs[li*QST+c]   = v.x * 0.125f; Qs[li*QST+c+1] = v.y * 0.125f;
            Qs[li*QST+c+2] = v.z * 0.125f; Qs[li*QST+c+3] = v.w * 0.125f;
        }
    }
    float m_i[4], l_i[4], o[4][4];
    #pragma unroll
    for (int v = 0; v < 4; v++) {
        m_i[v] = -1e30f; l_i[v] = 0.f;
        o[v][0] = o[v][1] = o[v][2] = o[v][3] = 0.f;
    }

    for (int kt = 0; kt <= qt; kt++) {
        __syncthreads();
        const int kbase = kt * 64;
        const float* gk = qkv + (srow + kbase + li) * (size_t)3072 + 1024 + h * 64;
        const float* gv = qkv + (srow + kbase + li) * (size_t)3072 + 2048 + h * 64;
        #pragma unroll
        for (int u = 0; u < 4; u++) {
            const int c = lc0 + u * 16;
            float4 kv = *(const float4*)(gk + c);
            KP[li*QST+c]   = kv.x; KP[li*QST+c+1] = kv.y;
            KP[li*QST+c+2] = kv.z; KP[li*QST+c+3] = kv.w;
            float4 vv = *(const float4*)(gv + c);
            *(float4*)&Vs[li * 64 + c] = vv;
        }
        __syncthreads();
        float s[4][4];
        #pragma unroll
        for (int v = 0; v < 4; v++) s[v][0] = s[v][1] = s[v][2] = s[v][3] = 0.f;
        #pragma unroll 8
        for (int dd = 0; dd < 64; dd++) {
            float a[4], bf[4];
            #pragma unroll
            for (int v = 0; v < 4; v++) a[v]  = Qs[(ty * 4 + v) * QST + dd];
            #pragma unroll
            for (int u = 0; u < 4; u++) bf[u] = KP[(tx * 4 + u) * QST + dd];
            #pragma unroll
            for (int v = 0; v < 4; v++)
                #pragma unroll
                for (int u = 0; u < 4; u++) s[v][u] += a[v] * bf[u];
        }
        if (kt == qt) {
            #pragma unroll
            for (int v = 0; v < 4; v++)
                #pragma unroll
                for (int u = 0; u < 4; u++)
                    if (tx * 4 + u > ty * 4 + v) s[v][u] = -1e30f;
        }
        float mnew[4], alpha[4], p[4][4], rsum[4];
        #pragma unroll
        for (int v = 0; v < 4; v++) {
            float mx = fmaxf(fmaxf(s[v][0], s[v][1]), fmaxf(s[v][2], s[v][3]));
            #pragma unroll
            for (int off = 8; off; off >>= 1)
                mx = fmaxf(mx, __shfl_xor_sync(0xffffffffu, mx, off));
            mnew[v]  = fmaxf(m_i[v], mx);
            alpha[v] = __expf(m_i[v] - mnew[v]);
            float rs = 0.f;
            #pragma unroll
            for (int u = 0; u < 4; u++) { p[v][u] = __expf(s[v][u] - mnew[v]); rs += p[v][u]; }
            #pragma unroll
            for (int off = 8; off; off >>= 1)
                rs += __shfl_xor_sync(0xffffffffu, rs, off);
            rsum[v] = rs;
        }
        #pragma unroll
        for (int v = 0; v < 4; v++) {
            l_i[v] = alpha[v] * l_i[v] + rsum[v];
            m_i[v] = mnew[v];
            o[v][0] *= alpha[v]; o[v][1] *= alpha[v]; o[v][2] *= alpha[v]; o[v][3] *= alpha[v];
        }
        __syncthreads();
        #pragma unroll
        for (int v = 0; v < 4; v++)
            #pragma unroll
            for (int u = 0; u < 4; u++)
                KP[(ty * 4 + v) * QST + tx * 4 + u] = p[v][u];
        __syncthreads();
        #pragma unroll 4
        for (int jj = 0; jj < 64; jj++) {
            float4 bv = *(const float4*)&Vs[jj * 64 + tx * 4];
            #pragma unroll
            for (int v = 0; v < 4; v++) {
                float a = KP[(ty * 4 + v) * QST + jj];
                o[v][0] += a * bv.x; o[v][1] += a * bv.y;
                o[v][2] += a * bv.z; o[v][3] += a * bv.w;
            }
        }
    }
    #pragma unroll
    for (int v = 0; v < 4; v++) {
        const float inv = 1.f / l_i[v];
        const int qi = qbase + ty * 4 + v;
        float4 ov = make_float4(o[v][0]*inv, o[v][1]*inv, o[v][2]*inv, o[v][3]*inv);
        uint2 hh, ll;
        hh.x = pack_bf2(ov.x, ov.y); hh.y = pack_bf2(ov.z, ov.w);
        ll.x = pack_bf2(ov.x - bf_hi(ov.x), ov.y - bf_hi(ov.y));
        ll.y = pack_bf2(ov.z - bf_hi(ov.z), ov.w - bf_hi(ov.w));
        const size_t oo = (srow + qi) * (size_t)DMODEL + h * 64 + tx * 4;
        *(uint2*)(outh + oo) = hh;
        *(uint2*)(outl + oo) = ll;
    }
}

// ------------------------------ launcher ------------------------------------
extern "C" void kernel_launch(void* const* d_in, const int* in_sizes, int n_in,
                              void* d_out, int out_size)
{
    (void)in_sizes; (void)n_in; (void)out_size;
    const float* prev  = (const float*)d_in[0];
    const float* memkv = (const float*)d_in[1];
    const float* gval  = (const float*)d_in[2];
    const float* ln1g  = (const float*)d_in[3];
    const float* ln1b  = (const float*)d_in[4];
    const float* attnw = (const float*)d_in[5];
    const float* attnb = (const float*)d_in[6];
    const float* cprw  = (const float*)d_in[7];
    const float* cprb  = (const float*)d_in[8];
    const float* ln2g  = (const float*)d_in[9];
    const float* ln2b  = (const float*)d_in[10];
    const float* fcw   = (const float*)d_in[11];
    const float* fcb   = (const float*)d_in[12];
    const float* pw    = (const float*)d_in[13];
    const float* pb    = (const float*)d_in[14];
    float* out = (float*)d_out;

    float *qkv, *mem, *hid;
    __nv_bfloat16 *h1h, *h1l, *atth, *attl, *h2h, *h2l, *ffh, *ffl;
    __nv_bfloat16 *wqh, *wql, *wph, *wpl, *wfh, *wfl, *woh, *wol;
    cudaGetSymbolAddress((void**)&qkv, g_qkv);
    cudaGetSymbolAddress((void**)&mem, g_mem);
    cudaGetSymbolAddress((void**)&hid, g_hid);
    cudaGetSymbolAddress((void**)&h1h, g_h1h);  cudaGetSymbolAddress((void**)&h1l, g_h1l);
    cudaGetSymbolAddress((void**)&atth, g_atth); cudaGetSymbolAddress((void**)&attl, g_attl);
    cudaGetSymbolAddress((void**)&h2h, g_h2h);  cudaGetSymbolAddress((void**)&h2l, g_h2l);
    cudaGetSymbolAddress((void**)&ffh, g_ffh);  cudaGetSymbolAddress((void**)&ffl, g_ffl);
    cudaGetSymbolAddress((void**)&wqh, g_wqh);  cudaGetSymbolAddress((void**)&wql, g_wql);
    cudaGetSymbolAddress((void**)&wph, g_wph);  cudaGetSymbolAddress((void**)&wpl, g_wpl);
    cudaGetSymbolAddress((void**)&wfh, g_wfh);  cudaGetSymbolAddress((void**)&wfl, g_wfl);
    cudaGetSymbolAddress((void**)&woh, g_woh);  cudaGetSymbolAddress((void**)&wol, g_wol);

    cudaFuncSetAttribute(flash_kernel, cudaFuncAttributeMaxDynamicSharedMemorySize, FLASH_SMEM);
    cudaFuncSetAttribute(gemm_mma_kernel<0>, cudaFuncAttributeMaxDynamicSharedMemorySize, GEMM_SMEM);
    cudaFuncSetAttribute(gemm_mma_kernel<1>, cudaFuncAttributeMaxDynamicSharedMemorySize, GEMM_SMEM);
    cudaFuncSetAttribute(gemm_mma_kernel<2>, cudaFuncAttributeMaxDynamicSharedMemorySize, GEMM_SMEM);
    cudaFuncSetAttribute(gemm_mma_kernel<3>, cudaFuncAttributeMaxDynamicSharedMemorySize, GEMM_SMEM);

    // 0) weight converts (transpose + bf16 split)
    wconv_kernel<<<dim3(3*DMODEL/32, DMODEL/32), 256>>>(attnw, wqh, wql, DMODEL, 3*DMODEL);
    wconv_kernel<<<dim3(DMODEL/32,   DMODEL/32), 256>>>(cprw, wph, wpl, DMODEL, DMODEL);
    wconv_kernel<<<dim3(4*DMODEL/32, DMODEL/32), 256>>>(fcw, wfh, wfl, DMODEL, 4*DMODEL);
    wconv_kernel<<<dim3(DMODEL/32, 4*DMODEL/32), 256>>>(pw, woh, wol, 4*DMODEL, DMODEL);
    // 1) LN1 -> h1 hi/lo
    ln_kernel<<<ROWS, 256>>>(prev, ln1g, ln1b, h1h, h1l);
    // 2) qkv = h1 @ c_attn + b (f32)
    gemm_mma_kernel<0><<<dim3(24, 16), 256, GEMM_SMEM>>>(h1h, h1l, wqh, wql, attnb,
        qkv, nullptr, nullptr, ROWS, 3*DMODEL, DMODEL, nullptr, nullptr, nullptr);
    // 3) memory attention
    memattn_kernel<<<ROWS, 256>>>(qkv, memkv, mem);
    // 4) causal self-attention -> att hi/lo
    flash_kernel<<<dim3(SEQ/64, BS_*NH), 256, FLASH_SMEM>>>(qkv, atth, attl);
    // 5) hid = (1-g)*(att@c_proj+b) + g*mem + prev
    gemm_mma_kernel<1><<<dim3(8, 16), 256, GEMM_SMEM>>>(atth, attl, wph, wpl, cprb,
        hid, nullptr, nullptr, ROWS, DMODEL, DMODEL, mem, prev, gval);
    // 6) LN2 -> h2 hi/lo
    ln_kernel<<<ROWS, 256>>>(hid, ln2g, ln2b, h2h, h2l);
    // 7) ff = gelu(h2 @ fc + b) -> hi/lo
    gemm_mma_kernel<2><<<dim3(32, 16), 256, GEMM_SMEM>>>(h2h, h2l, wfh, wfl, fcb,
        nullptr, ffh, ffl, ROWS, 4*DMODEL, DMODEL, nullptr, nullptr, nullptr);
    // 8) out = ff @ proj + b + hid
    gemm_mma_kernel<3><<<dim3(8, 16), 256, GEMM_SMEM>>>(ffh, ffl, woh, wol, pb,
        out, nullptr, nullptr, ROWS, DMODEL, 4*DMODEL, hid, nullptr, nullptr);
}